// round 9
// baseline (speedup 1.0000x reference)
#include <cuda_runtime.h>
#include <cuda_bf16.h>
#include <math.h>

#define B_    32
#define H_    32
#define D_    128
#define HID_  4096
#define TH_   12288      // 3*HID
#define BS_   64
#define NBLK_ 16
#define KSPLIT 32

__device__ float g_part[KSPLIT][B_ * TH_];  // qkv partials (L2-resident)
__device__ float g_qkv[B_ * TH_];           // [b][j]; j<4096 q, ..8191 k, .. v
__device__ float g_attn[B_ * HID_];
__device__ float g_cs[B_][64][2];           // rope cos/sin table

typedef unsigned long long u64;

__device__ __forceinline__ u64 pack2(float lo, float hi) {
    u64 r; asm("mov.b64 %0, {%1, %2};" : "=l"(r) : "f"(lo), "f"(hi)); return r;
}
__device__ __forceinline__ u64 fma2(u64 a, u64 b, u64 c) {
    u64 d; asm("fma.rn.f32x2 %0, %1, %2, %3;" : "=l"(d) : "l"(a), "l"(b), "l"(c)); return d;
}
__device__ __forceinline__ float lo2(u64 a) {
    float lo, hi; asm("mov.b64 {%0, %1}, %2;" : "=f"(lo), "=f"(hi) : "l"(a)); return lo;
}
__device__ __forceinline__ float hi2(u64 a) {
    float lo, hi; asm("mov.b64 {%0, %1}, %2;" : "=f"(lo), "=f"(hi) : "l"(a)); return hi;
}

// ---------------------------------------------------------------------------
// Kernel 1: qkv partials. grid (48 j-tiles, KSPLIT=32), block 256, 3 blk/SM.
// Thread = 4 j x 8 b; W prefetch RING depth 4 (distance 4 k-iters) so the
// DRAM/L2 latency of the W stream is covered by 6 warps/SMSP x 160cyc.
// ---------------------------------------------------------------------------
__global__ __launch_bounds__(256, 3) void qkv_part_kernel(const float* __restrict__ hidden,
                                                          const float* __restrict__ W) {
    __shared__ u64 shd[128][34];         // [k][b] duplicated pairs, 34.8 KB
    const int lane = threadIdx.x & 31;
    const int wid  = threadIdx.x >> 5;
    const int j0   = blockIdx.x * 256 + (wid >> 2) * 128 + lane * 4;
    const int bg   = (wid & 3) * 8;
    const int k0   = blockIdx.y * 128;   // 128 k per block

    u64 acc[2][8];   // [j-pair][batch]
#pragma unroll
    for (int jp = 0; jp < 2; jp++)
#pragma unroll
        for (int b = 0; b < 8; b++) acc[jp][b] = 0ull;

    // hidden tile (128 k x 32 b), duplicated packing
#pragma unroll
    for (int t = 0; t < 4; t++) {
        int idx = threadIdx.x + t * 256;
        int kg  = idx >> 5;
        int b   = idx & 31;
        float4 h4 = *(const float4*)&hidden[b * HID_ + k0 + kg * 4];
        shd[kg * 4 + 0][b] = pack2(h4.x, h4.x);
        shd[kg * 4 + 1][b] = pack2(h4.y, h4.y);
        shd[kg * 4 + 2][b] = pack2(h4.z, h4.z);
        shd[kg * 4 + 3][b] = pack2(h4.w, h4.w);
    }
    __syncthreads();

    const float* wp = W + (size_t)k0 * TH_ + j0;
    float4 wring[4];
#pragma unroll
    for (int u = 0; u < 4; u++)
        wring[u] = *(const float4*)(wp + (size_t)u * TH_);
    const float* wpn = wp + 4 * (size_t)TH_;   // next row to fetch

#pragma unroll 4
    for (int kk = 0; kk < 128; kk++) {
        float4 wcur = wring[kk & 3];
        if (kk + 4 < 128) {                    // refill slot: 4-iter distance
            wring[kk & 3] = *(const float4*)wpn;
            wpn += TH_;
        }
        ulonglong2 wpair = *(const ulonglong2*)&wcur;     // 2 f32x2 j-pairs
        const u64* hrow = &shd[kk][bg];
        ulonglong2 h01 = *(const ulonglong2*)&hrow[0];
        ulonglong2 h23 = *(const ulonglong2*)&hrow[2];
        ulonglong2 h45 = *(const ulonglong2*)&hrow[4];
        ulonglong2 h67 = *(const ulonglong2*)&hrow[6];
        acc[0][0] = fma2(wpair.x, h01.x, acc[0][0]);
        acc[1][0] = fma2(wpair.y, h01.x, acc[1][0]);
        acc[0][1] = fma2(wpair.x, h01.y, acc[0][1]);
        acc[1][1] = fma2(wpair.y, h01.y, acc[1][1]);
        acc[0][2] = fma2(wpair.x, h23.x, acc[0][2]);
        acc[1][2] = fma2(wpair.y, h23.x, acc[1][2]);
        acc[0][3] = fma2(wpair.x, h23.y, acc[0][3]);
        acc[1][3] = fma2(wpair.y, h23.y, acc[1][3]);
        acc[0][4] = fma2(wpair.x, h45.x, acc[0][4]);
        acc[1][4] = fma2(wpair.y, h45.x, acc[1][4]);
        acc[0][5] = fma2(wpair.x, h45.y, acc[0][5]);
        acc[1][5] = fma2(wpair.y, h45.y, acc[1][5]);
        acc[0][6] = fma2(wpair.x, h67.x, acc[0][6]);
        acc[1][6] = fma2(wpair.y, h67.x, acc[1][6]);
        acc[0][7] = fma2(wpair.x, h67.y, acc[0][7]);
        acc[1][7] = fma2(wpair.y, h67.y, acc[1][7]);
    }

    float* outp = &g_part[blockIdx.y][0];
#pragma unroll
    for (int b = 0; b < 8; b++) {
        float4 o = make_float4(lo2(acc[0][b]), hi2(acc[0][b]),
                               lo2(acc[1][b]), hi2(acc[1][b]));
        *(float4*)&outp[(bg + b) * TH_ + j0] = o;
    }
}

// Reduce KSPLIT partials -> g_qkv. grid 384, block 256, float4 per thread.
__global__ __launch_bounds__(256) void qkv_reduce_kernel(int dummy) {
    int i = (blockIdx.x * 256 + threadIdx.x) * 4;
    float4 r = *(const float4*)&g_part[0][i];
#pragma unroll
    for (int p = 1; p < KSPLIT; p++) {
        float4 a = *(const float4*)&g_part[p][i];
        r.x += a.x; r.y += a.y; r.z += a.z; r.w += a.w;
    }
    *(float4*)&g_qkv[i] = r;
}

// ---------------------------------------------------------------------------
// Kernel 2a: rope table (only DP math, 2048 threads)
// ---------------------------------------------------------------------------
__global__ __launch_bounds__(64) void rope_table(const int* __restrict__ hist) {
    const int b = blockIdx.x;
    const int i = threadIdx.x;
    double invd = exp(-(double)i / 64.0 * 9.210340371976184);  // ln(10000)
    double angd = fmod((double)hist[b] * invd, 6.283185307179586476925286766559);
    g_cs[b][i][0] = cosf((float)angd);
    g_cs[b][i][1] = sinf((float)angd);
}

// Kernel 2b: apply rope to q,k. grid (32, 64): y = part*32+h. block 128.
__global__ __launch_bounds__(128) void rope_apply(int dummy) {
    const int b    = blockIdx.x;
    const int part = blockIdx.y >> 5;
    const int h    = blockIdx.y & 31;
    const int d    = threadIdx.x;
    const float c = g_cs[b][d & 63][0];
    const float s = g_cs[b][d & 63][1];

    float* p = &g_qkv[b * TH_ + part * HID_ + h * D_];
    float x  = p[d];
    float xr = (d < 64) ? -p[d + 64] : p[d - 64];
    __syncthreads();
    p[d] = x * c + xr * s;
}

// ---------------------------------------------------------------------------
// Kernel 3: attention, two-phase. grid = B*H blocks, 256 threads.
// ---------------------------------------------------------------------------
__global__ __launch_bounds__(256) void attn_kernel(const float* __restrict__ kcache,
                                                   const float* __restrict__ vcache,
                                                   const int* __restrict__ hist,
                                                   const int* __restrict__ boff) {
    const int b = blockIdx.x >> 5;
    const int h = blockIdx.x & 31;
    const int tid  = threadIdx.x;
    const int lane = tid & 31;
    const int wid  = tid >> 5;

    __shared__ int   s_blk[NBLK_];
    __shared__ float s_sc[1024];
    __shared__ float s_red[8];
    __shared__ float s_half[128];

    if (tid < NBLK_) s_blk[tid] = boff[b * NBLK_ + tid];
    __syncthreads();

    const int pos = hist[b];
    const float scale = 0.08838834764831845f;  // 1/sqrt(128)
    const float4 q4 = *(const float4*)&g_qkv[b * TH_ + h * D_ + lane * 4];

    // ---- phase 1: scores ----
    float mloc = -1e30f;
    int s = wid;
    for (; s + 24 < pos; s += 32) {
        float4 k[4];
        int    sp[4];
#pragma unroll
        for (int u = 0; u < 4; u++) {
            sp[u] = s + u * 8;
            int a = ((s_blk[sp[u] >> 6] * BS_ + (sp[u] & 63)) * H_ + h) * D_;
            k[u] = *(const float4*)&kcache[a + lane * 4];
        }
        float dt[4];
#pragma unroll
        for (int u = 0; u < 4; u++)
            dt[u] = q4.x * k[u].x + q4.y * k[u].y + q4.z * k[u].z + q4.w * k[u].w;
#pragma unroll
        for (int o = 16; o > 0; o >>= 1)
#pragma unroll
            for (int u = 0; u < 4; u++)
                dt[u] += __shfl_xor_sync(0xffffffffu, dt[u], o);
#pragma unroll
        for (int u = 0; u < 4; u++) {
            dt[u] *= scale;
            mloc = fmaxf(mloc, dt[u]);
            if (lane == 0) s_sc[sp[u]] = dt[u];
        }
    }
    for (; s < pos; s += 8) {
        int a0 = ((s_blk[s >> 6] * BS_ + (s & 63)) * H_ + h) * D_;
        float4 k0 = *(const float4*)&kcache[a0 + lane * 4];
        float d0 = q4.x * k0.x + q4.y * k0.y + q4.z * k0.z + q4.w * k0.w;
#pragma unroll
        for (int o = 16; o > 0; o >>= 1) d0 += __shfl_xor_sync(0xffffffffu, d0, o);
        d0 *= scale;
        mloc = fmaxf(mloc, d0);
        if (lane == 0) s_sc[s] = d0;
    }
    if ((pos & 7) == wid) {      // fresh k at s == pos (ref writes cache first)
        const float* kp = &g_qkv[b * TH_ + HID_ + h * D_];
        float4 k0 = *(const float4*)&kp[lane * 4];
        float d0 = q4.x * k0.x + q4.y * k0.y + q4.z * k0.z + q4.w * k0.w;
#pragma unroll
        for (int o = 16; o > 0; o >>= 1) d0 += __shfl_xor_sync(0xffffffffu, d0, o);
        d0 *= scale;
        mloc = fmaxf(mloc, d0);
        if (lane == 0) s_sc[pos] = d0;
    }

    if (lane == 0) s_red[wid] = mloc;
    __syncthreads();
    float M = -1e30f;
#pragma unroll
    for (int w = 0; w < 8; w++) M = fmaxf(M, s_red[w]);

    float lsum = 0.f;
    for (int i = tid; i <= pos; i += 256) {
        float p = __expf(s_sc[i] - M);
        s_sc[i] = p;
        lsum += p;
    }
#pragma unroll
    for (int o = 16; o > 0; o >>= 1) lsum += __shfl_xor_sync(0xffffffffu, lsum, o);
    __syncthreads();
    if (lane == 0) s_red[wid] = lsum;
    __syncthreads();
    float L = 0.f;
#pragma unroll
    for (int w = 0; w < 8; w++) L += s_red[w];
    const float invL = 1.f / L;

    // ---- phase 2: out[d] = sum_s p[s] * v[s][d], coalesced over d ----
    const int d    = tid & 127;
    const int half = tid >> 7;
    float acc = 0.f;
#pragma unroll 8
    for (int s2 = half; s2 < pos; s2 += 2) {
        int base = ((s_blk[s2 >> 6] * BS_ + (s2 & 63)) * H_ + h) * D_;
        acc += s_sc[s2] * vcache[base + d];
    }
    if ((pos & 1) == half)
        acc += s_sc[pos] * g_qkv[b * TH_ + 2 * HID_ + h * D_ + d];

    if (half == 0) s_half[d] = acc;
    __syncthreads();
    if (half == 1)
        g_attn[b * HID_ + h * D_ + d] = (acc + s_half[d]) * invL;
}

// ---------------------------------------------------------------------------
// Kernel 4: out = attn @ Wo^T, f32x2. block 128, warp = 2 rows x 16 batches.
// grid 1024 = 512 row-tiles x 2 batch-halves.
// ---------------------------------------------------------------------------
__global__ __launch_bounds__(128) void oproj_kernel(const float* __restrict__ Wo,
                                                    float* __restrict__ out) {
    __shared__ float s_attn[16][256];
    const int lane = threadIdx.x & 31;
    const int wid  = threadIdx.x >> 5;
    const int tile = blockIdx.x >> 1;
    const int bh   = (blockIdx.x & 1) * 16;
    const int i0   = tile * 8 + wid * 2;

    u64 acc[2][16];
#pragma unroll
    for (int r = 0; r < 2; r++)
#pragma unroll
        for (int b = 0; b < 16; b++) acc[r][b] = 0ull;

    for (int jt = 0; jt < HID_; jt += 256) {
        __syncthreads();
#pragma unroll
        for (int t = 0; t < 8; t++) {
            int idx = threadIdx.x + t * 128;
            int b   = idx >> 6;
            int jj  = (idx & 63) << 2;
            *(float4*)&s_attn[b][jj] = *(const float4*)&g_attn[(bh + b) * HID_ + jt + jj];
        }
        __syncthreads();

        const float* w = Wo + (size_t)i0 * HID_ + jt;
#pragma unroll
        for (int part = 0; part < 2; part++) {
            int j0 = part * 128 + lane * 4;
            ulonglong2 w0 = *(const ulonglong2*)&w[j0];
            ulonglong2 w1 = *(const ulonglong2*)&w[HID_ + j0];
#pragma unroll
            for (int b = 0; b < 16; b++) {
                ulonglong2 a = *(const ulonglong2*)&s_attn[b][j0];
                acc[0][b] = fma2(a.x, w0.x, acc[0][b]);
                acc[0][b] = fma2(a.y, w0.y, acc[0][b]);
                acc[1][b] = fma2(a.x, w1.x, acc[1][b]);
                acc[1][b] = fma2(a.y, w1.y, acc[1][b]);
            }
        }
    }

#pragma unroll
    for (int r = 0; r < 2; r++) {
        float res = 0.f;
#pragma unroll
        for (int b = 0; b < 16; b++) {
            float v = lo2(acc[r][b]) + hi2(acc[r][b]);
#pragma unroll
            for (int o = 16; o > 0; o >>= 1) v += __shfl_xor_sync(0xffffffffu, v, o);
            if (lane == b) res = v;
        }
        if (lane < 16) out[(bh + lane) * HID_ + i0 + r] = res;
    }
}

// ---------------------------------------------------------------------------
extern "C" void kernel_launch(void* const* d_in, const int* in_sizes, int n_in,
                              void* d_out, int out_size) {
    const float* hidden = (const float*)d_in[0];
    const float* W      = (const float*)d_in[1];
    const float* Wo     = (const float*)d_in[2];
    const float* kcache = (const float*)d_in[3];
    const float* vcache = (const float*)d_in[4];
    const int*   hist   = (const int*)d_in[5];
    const int*   boff   = (const int*)d_in[6];
    float*       out    = (float*)d_out;

    qkv_part_kernel<<<dim3(TH_ / 256, KSPLIT), 256>>>(hidden, W);
    qkv_reduce_kernel<<<B_ * TH_ / 1024, 256>>>(0);
    rope_table<<<B_, 64>>>(hist);
    rope_apply<<<dim3(B_, 2 * H_), 128>>>(0);
    attn_kernel<<<B_ * H_, 256>>>(kcache, vcache, hist, boff);
    oproj_kernel<<<1024, 128>>>(Wo, out);
}

// round 10
// speedup vs baseline: 1.2140x; 1.2140x over previous
#include <cuda_runtime.h>
#include <cuda_bf16.h>
#include <math.h>

#define B_    32
#define H_    32
#define D_    128
#define HID_  4096
#define TH_   12288      // 3*HID
#define BS_   64
#define NBLK_ 16
#define KSPLIT 32

__device__ float g_part[KSPLIT][B_ * TH_];  // qkv partials
__device__ float g_qkv[B_ * TH_];           // [b][j]; j<4096 q, ..8191 k, .. v
__device__ float g_attn[B_ * HID_];
__device__ float g_cs[B_][64][2];           // rope cos/sin table

typedef unsigned long long u64;

__device__ __forceinline__ u64 pack2(float lo, float hi) {
    u64 r; asm("mov.b64 %0, {%1, %2};" : "=l"(r) : "f"(lo), "f"(hi)); return r;
}
__device__ __forceinline__ u64 fma2(u64 a, u64 b, u64 c) {
    u64 d; asm("fma.rn.f32x2 %0, %1, %2, %3;" : "=l"(d) : "l"(a), "l"(b), "l"(c)); return d;
}
__device__ __forceinline__ float lo2(u64 a) {
    float lo, hi; asm("mov.b64 {%0, %1}, %2;" : "=f"(lo), "=f"(hi) : "l"(a)); return lo;
}
__device__ __forceinline__ float hi2(u64 a) {
    float lo, hi; asm("mov.b64 {%0, %1}, %2;" : "=f"(lo), "=f"(hi) : "l"(a)); return hi;
}

// ---------------------------------------------------------------------------
// Kernel 1 (R8 config — best measured): grid (24 j-tiles, KSPLIT=32), blk 256.
// Thread = 8 j (two rows of 4, 128 apart) x 8 batches; 2-deep W buffer.
// ---------------------------------------------------------------------------
__global__ __launch_bounds__(256) void qkv_part_kernel(const float* __restrict__ hidden,
                                                       const float* __restrict__ W) {
    __shared__ u64 shd[128][34];
    const int lane = threadIdx.x & 31;
    const int wid  = threadIdx.x >> 5;
    const int wg   = wid >> 2;
    const int bg   = (wid & 3) * 8;
    const int j0   = blockIdx.x * 512 + wg * 256 + lane * 4;
    const int k0   = blockIdx.y * 128;

    u64 acc[4][8];
#pragma unroll
    for (int jp = 0; jp < 4; jp++)
#pragma unroll
        for (int b = 0; b < 8; b++) acc[jp][b] = 0ull;

#pragma unroll
    for (int t = 0; t < 4; t++) {
        int idx = threadIdx.x + t * 256;
        int kg  = idx >> 5;
        int b   = idx & 31;
        float4 h4 = *(const float4*)&hidden[b * HID_ + k0 + kg * 4];
        shd[kg * 4 + 0][b] = pack2(h4.x, h4.x);
        shd[kg * 4 + 1][b] = pack2(h4.y, h4.y);
        shd[kg * 4 + 2][b] = pack2(h4.z, h4.z);
        shd[kg * 4 + 3][b] = pack2(h4.w, h4.w);
    }
    __syncthreads();

    const float* wp = W + (size_t)k0 * TH_ + j0;
    float4 wbuf[2][2][2];
#pragma unroll
    for (int u = 0; u < 2; u++) {
        wbuf[0][u][0] = *(const float4*)(wp + (size_t)u * TH_);
        wbuf[0][u][1] = *(const float4*)(wp + (size_t)u * TH_ + 128);
    }
    wp += 2 * (size_t)TH_;

#pragma unroll 4
    for (int kk = 0; kk < 128; kk += 2) {
        const int par = (kk >> 1) & 1;
        const int nxt = par ^ 1;
        if (kk + 2 < 128) {
#pragma unroll
            for (int u = 0; u < 2; u++) {
                wbuf[nxt][u][0] = *(const float4*)(wp + (size_t)u * TH_);
                wbuf[nxt][u][1] = *(const float4*)(wp + (size_t)u * TH_ + 128);
            }
            wp += 2 * (size_t)TH_;
        }
#pragma unroll
        for (int u = 0; u < 2; u++) {
            ulonglong2 wA = *(const ulonglong2*)&wbuf[par][u][0];
            ulonglong2 wB = *(const ulonglong2*)&wbuf[par][u][1];
            const u64* hrow = &shd[kk + u][bg];
            ulonglong2 h01 = *(const ulonglong2*)&hrow[0];
            ulonglong2 h23 = *(const ulonglong2*)&hrow[2];
            ulonglong2 h45 = *(const ulonglong2*)&hrow[4];
            ulonglong2 h67 = *(const ulonglong2*)&hrow[6];
            acc[0][0] = fma2(wA.x, h01.x, acc[0][0]);
            acc[1][0] = fma2(wA.y, h01.x, acc[1][0]);
            acc[2][0] = fma2(wB.x, h01.x, acc[2][0]);
            acc[3][0] = fma2(wB.y, h01.x, acc[3][0]);
            acc[0][1] = fma2(wA.x, h01.y, acc[0][1]);
            acc[1][1] = fma2(wA.y, h01.y, acc[1][1]);
            acc[2][1] = fma2(wB.x, h01.y, acc[2][1]);
            acc[3][1] = fma2(wB.y, h01.y, acc[3][1]);
            acc[0][2] = fma2(wA.x, h23.x, acc[0][2]);
            acc[1][2] = fma2(wA.y, h23.x, acc[1][2]);
            acc[2][2] = fma2(wB.x, h23.x, acc[2][2]);
            acc[3][2] = fma2(wB.y, h23.x, acc[3][2]);
            acc[0][3] = fma2(wA.x, h23.y, acc[0][3]);
            acc[1][3] = fma2(wA.y, h23.y, acc[1][3]);
            acc[2][3] = fma2(wB.x, h23.y, acc[2][3]);
            acc[3][3] = fma2(wB.y, h23.y, acc[3][3]);
            acc[0][4] = fma2(wA.x, h45.x, acc[0][4]);
            acc[1][4] = fma2(wA.y, h45.x, acc[1][4]);
            acc[2][4] = fma2(wB.x, h45.x, acc[2][4]);
            acc[3][4] = fma2(wB.y, h45.x, acc[3][4]);
            acc[0][5] = fma2(wA.x, h45.y, acc[0][5]);
            acc[1][5] = fma2(wA.y, h45.y, acc[1][5]);
            acc[2][5] = fma2(wB.x, h45.y, acc[2][5]);
            acc[3][5] = fma2(wB.y, h45.y, acc[3][5]);
            acc[0][6] = fma2(wA.x, h67.x, acc[0][6]);
            acc[1][6] = fma2(wA.y, h67.x, acc[1][6]);
            acc[2][6] = fma2(wB.x, h67.x, acc[2][6]);
            acc[3][6] = fma2(wB.y, h67.x, acc[3][6]);
            acc[0][7] = fma2(wA.x, h67.y, acc[0][7]);
            acc[1][7] = fma2(wA.y, h67.y, acc[1][7]);
            acc[2][7] = fma2(wB.x, h67.y, acc[2][7]);
            acc[3][7] = fma2(wB.y, h67.y, acc[3][7]);
        }
    }

    float* outp = &g_part[blockIdx.y][0];
#pragma unroll
    for (int b = 0; b < 8; b++) {
        float4 oA = make_float4(lo2(acc[0][b]), hi2(acc[0][b]),
                                lo2(acc[1][b]), hi2(acc[1][b]));
        float4 oB = make_float4(lo2(acc[2][b]), hi2(acc[2][b]),
                                lo2(acc[3][b]), hi2(acc[3][b]));
        *(float4*)&outp[(bg + b) * TH_ + j0]       = oA;
        *(float4*)&outp[(bg + b) * TH_ + j0 + 128] = oB;
    }
}

__global__ __launch_bounds__(256) void qkv_reduce_kernel(int dummy) {
    int i = (blockIdx.x * 256 + threadIdx.x) * 4;
    float4 r = *(const float4*)&g_part[0][i];
#pragma unroll
    for (int p = 1; p < KSPLIT; p++) {
        float4 a = *(const float4*)&g_part[p][i];
        r.x += a.x; r.y += a.y; r.z += a.z; r.w += a.w;
    }
    *(float4*)&g_qkv[i] = r;
}

// ---------------------------------------------------------------------------
__global__ __launch_bounds__(64) void rope_table(const int* __restrict__ hist) {
    const int b = blockIdx.x;
    const int i = threadIdx.x;
    double invd = exp(-(double)i / 64.0 * 9.210340371976184);  // ln(10000)
    double angd = fmod((double)hist[b] * invd, 6.283185307179586476925286766559);
    g_cs[b][i][0] = cosf((float)angd);
    g_cs[b][i][1] = sinf((float)angd);
}

__global__ __launch_bounds__(128) void rope_apply(int dummy) {
    const int b    = blockIdx.x;
    const int part = blockIdx.y >> 5;
    const int h    = blockIdx.y & 31;
    const int d    = threadIdx.x;
    const float c = g_cs[b][d & 63][0];
    const float s = g_cs[b][d & 63][1];

    float* p = &g_qkv[b * TH_ + part * HID_ + h * D_];
    float x  = p[d];
    float xr = (d < 64) ? -p[d + 64] : p[d - 64];
    __syncthreads();
    p[d] = x * c + xr * s;
}

// ---------------------------------------------------------------------------
// Kernel 3: attention, two-phase. grid = B*H blocks, 256 threads.
// Phase 2 rewritten: warp = position stripe, lane = d-quad, LDG.128 V loads
// with 4-position unroll (mirrors phase 1), cross-warp reduce via smem.
// ---------------------------------------------------------------------------
__global__ __launch_bounds__(256) void attn_kernel(const float* __restrict__ kcache,
                                                   const float* __restrict__ vcache,
                                                   const int* __restrict__ hist,
                                                   const int* __restrict__ boff) {
    const int b = blockIdx.x >> 5;
    const int h = blockIdx.x & 31;
    const int tid  = threadIdx.x;
    const int lane = tid & 31;
    const int wid  = tid >> 5;

    __shared__ int   s_blk[NBLK_];
    __shared__ float s_sc[1024];
    __shared__ float s_red[8];
    __shared__ float s_acc[8][128];

    if (tid < NBLK_) s_blk[tid] = boff[b * NBLK_ + tid];
    __syncthreads();

    const int pos = hist[b];
    const float scale = 0.08838834764831845f;  // 1/sqrt(128)
    const float4 q4 = *(const float4*)&g_qkv[b * TH_ + h * D_ + lane * 4];

    // ---- phase 1: scores ----
    float mloc = -1e30f;
    int s = wid;
    for (; s + 24 < pos; s += 32) {
        float4 k[4];
        int    sp[4];
#pragma unroll
        for (int u = 0; u < 4; u++) {
            sp[u] = s + u * 8;
            int a = ((s_blk[sp[u] >> 6] * BS_ + (sp[u] & 63)) * H_ + h) * D_;
            k[u] = *(const float4*)&kcache[a + lane * 4];
        }
        float dt[4];
#pragma unroll
        for (int u = 0; u < 4; u++)
            dt[u] = q4.x * k[u].x + q4.y * k[u].y + q4.z * k[u].z + q4.w * k[u].w;
#pragma unroll
        for (int o = 16; o > 0; o >>= 1)
#pragma unroll
            for (int u = 0; u < 4; u++)
                dt[u] += __shfl_xor_sync(0xffffffffu, dt[u], o);
#pragma unroll
        for (int u = 0; u < 4; u++) {
            dt[u] *= scale;
            mloc = fmaxf(mloc, dt[u]);
            if (lane == 0) s_sc[sp[u]] = dt[u];
        }
    }
    for (; s < pos; s += 8) {
        int a0 = ((s_blk[s >> 6] * BS_ + (s & 63)) * H_ + h) * D_;
        float4 k0 = *(const float4*)&kcache[a0 + lane * 4];
        float d0 = q4.x * k0.x + q4.y * k0.y + q4.z * k0.z + q4.w * k0.w;
#pragma unroll
        for (int o = 16; o > 0; o >>= 1) d0 += __shfl_xor_sync(0xffffffffu, d0, o);
        d0 *= scale;
        mloc = fmaxf(mloc, d0);
        if (lane == 0) s_sc[s] = d0;
    }
    if ((pos & 7) == wid) {      // fresh k at s == pos (ref writes cache first)
        const float* kp = &g_qkv[b * TH_ + HID_ + h * D_];
        float4 k0 = *(const float4*)&kp[lane * 4];
        float d0 = q4.x * k0.x + q4.y * k0.y + q4.z * k0.z + q4.w * k0.w;
#pragma unroll
        for (int o = 16; o > 0; o >>= 1) d0 += __shfl_xor_sync(0xffffffffu, d0, o);
        d0 *= scale;
        mloc = fmaxf(mloc, d0);
        if (lane == 0) s_sc[pos] = d0;
    }

    if (lane == 0) s_red[wid] = mloc;
    __syncthreads();
    float M = -1e30f;
#pragma unroll
    for (int w = 0; w < 8; w++) M = fmaxf(M, s_red[w]);

    float lsum = 0.f;
    for (int i = tid; i <= pos; i += 256) {
        float p = __expf(s_sc[i] - M);
        s_sc[i] = p;
        lsum += p;
    }
#pragma unroll
    for (int o = 16; o > 0; o >>= 1) lsum += __shfl_xor_sync(0xffffffffu, lsum, o);
    __syncthreads();
    if (lane == 0) s_red[wid] = lsum;
    __syncthreads();
    float L = 0.f;
#pragma unroll
    for (int w = 0; w < 8; w++) L += s_red[w];
    const float invL = 1.f / L;

    // ---- phase 2: warp = position stripe, lane = d-quad, LDG.128 ----
    float4 a4 = make_float4(0.f, 0.f, 0.f, 0.f);
    s = wid;
    for (; s + 24 < pos; s += 32) {
        float4 v[4];
        float  pr[4];
#pragma unroll
        for (int u = 0; u < 4; u++) {
            int su = s + u * 8;
            int a  = ((s_blk[su >> 6] * BS_ + (su & 63)) * H_ + h) * D_;
            v[u]  = *(const float4*)&vcache[a + lane * 4];
            pr[u] = s_sc[su];
        }
#pragma unroll
        for (int u = 0; u < 4; u++) {
            a4.x += pr[u] * v[u].x;
            a4.y += pr[u] * v[u].y;
            a4.z += pr[u] * v[u].z;
            a4.w += pr[u] * v[u].w;
        }
    }
    for (; s < pos; s += 8) {
        int a = ((s_blk[s >> 6] * BS_ + (s & 63)) * H_ + h) * D_;
        float4 v = *(const float4*)&vcache[a + lane * 4];
        float  p = s_sc[s];
        a4.x += p * v.x; a4.y += p * v.y; a4.z += p * v.z; a4.w += p * v.w;
    }
    if ((pos & 7) == wid) {      // fresh v at s == pos
        const float* vp = &g_qkv[b * TH_ + 2 * HID_ + h * D_];
        float4 v = *(const float4*)&vp[lane * 4];
        float  p = s_sc[pos];
        a4.x += p * v.x; a4.y += p * v.y; a4.z += p * v.z; a4.w += p * v.w;
    }

    *(float4*)&s_acc[wid][lane * 4] = a4;
    __syncthreads();
    if (tid < 128) {
        float val = 0.f;
#pragma unroll
        for (int w = 0; w < 8; w++) val += s_acc[w][tid];
        g_attn[b * HID_ + h * D_ + tid] = val * invL;
    }
}

// ---------------------------------------------------------------------------
// Kernel 4: out = attn @ Wo^T, f32x2. block 128, warp = 2 rows x 16 batches.
// ---------------------------------------------------------------------------
__global__ __launch_bounds__(128) void oproj_kernel(const float* __restrict__ Wo,
                                                    float* __restrict__ out) {
    __shared__ float s_attn[16][256];
    const int lane = threadIdx.x & 31;
    const int wid  = threadIdx.x >> 5;
    const int tile = blockIdx.x >> 1;
    const int bh   = (blockIdx.x & 1) * 16;
    const int i0   = tile * 8 + wid * 2;

    u64 acc[2][16];
#pragma unroll
    for (int r = 0; r < 2; r++)
#pragma unroll
        for (int b = 0; b < 16; b++) acc[r][b] = 0ull;

    for (int jt = 0; jt < HID_; jt += 256) {
        __syncthreads();
#pragma unroll
        for (int t = 0; t < 8; t++) {
            int idx = threadIdx.x + t * 128;
            int b   = idx >> 6;
            int jj  = (idx & 63) << 2;
            *(float4*)&s_attn[b][jj] = *(const float4*)&g_attn[(bh + b) * HID_ + jt + jj];
        }
        __syncthreads();

        const float* w = Wo + (size_t)i0 * HID_ + jt;
#pragma unroll
        for (int part = 0; part < 2; part++) {
            int j0 = part * 128 + lane * 4;
            ulonglong2 w0 = *(const ulonglong2*)&w[j0];
            ulonglong2 w1 = *(const ulonglong2*)&w[HID_ + j0];
#pragma unroll
            for (int b = 0; b < 16; b++) {
                ulonglong2 a = *(const ulonglong2*)&s_attn[b][j0];
                acc[0][b] = fma2(a.x, w0.x, acc[0][b]);
                acc[0][b] = fma2(a.y, w0.y, acc[0][b]);
                acc[1][b] = fma2(a.x, w1.x, acc[1][b]);
                acc[1][b] = fma2(a.y, w1.y, acc[1][b]);
            }
        }
    }

#pragma unroll
    for (int r = 0; r < 2; r++) {
        float res = 0.f;
#pragma unroll
        for (int b = 0; b < 16; b++) {
            float v = lo2(acc[r][b]) + hi2(acc[r][b]);
#pragma unroll
            for (int o = 16; o > 0; o >>= 1) v += __shfl_xor_sync(0xffffffffu, v, o);
            if (lane == b) res = v;
        }
        if (lane < 16) out[(bh + lane) * HID_ + i0 + r] = res;
    }
}

// ---------------------------------------------------------------------------
extern "C" void kernel_launch(void* const* d_in, const int* in_sizes, int n_in,
                              void* d_out, int out_size) {
    const float* hidden = (const float*)d_in[0];
    const float* W      = (const float*)d_in[1];
    const float* Wo     = (const float*)d_in[2];
    const float* kcache = (const float*)d_in[3];
    const float* vcache = (const float*)d_in[4];
    const int*   hist   = (const int*)d_in[5];
    const int*   boff   = (const int*)d_in[6];
    float*       out    = (float*)d_out;

    qkv_part_kernel<<<dim3(TH_ / 512, KSPLIT), 256>>>(hidden, W);
    qkv_reduce_kernel<<<B_ * TH_ / 1024, 256>>>(0);
    rope_table<<<B_, 64>>>(hist);
    rope_apply<<<dim3(B_, 2 * H_), 128>>>(0);
    attn_kernel<<<B_ * H_, 256>>>(kcache, vcache, hist, boff);
    oproj_kernel<<<1024, 128>>>(Wo, out);
}